// round 3
// baseline (speedup 1.0000x reference)
#include <cuda_runtime.h>
#include <cuda_fp16.h>
#include <cstdint>
#include <stdint.h>

// Problem dims (fixed)
#define T_TOK 2048
#define D_DIM 1024
#define H_DIM 4096
#define E_NUM 8
#define K2    (E_NUM * H_DIM)   // 32768, fc2 K after folding probs into h

// GEMM tiling
#define BM 128
#define BN 128
#define BK 32
#define PADA 8   // halfs
#define PADB 8   // halfs
#define KSPLIT2 4

// ---------------- scratch (static device arrays; no allocation) ----------------
__device__ __half g_xh [T_TOK * D_DIM];
__device__ __half g_w1h[E_NUM * D_DIM * H_DIM];
__device__ __half g_w2h[E_NUM * H_DIM * D_DIM];   // flat [K2][D]
__device__ __half g_hb [ (size_t)T_TOK * K2 ];    // probs*gelu(fc1), fp16
__device__ float  g_probs[T_TOK * E_NUM];

// ---------------- fp32 -> fp16 conversion ----------------
template <int SEL>
__global__ void f2h_kernel(const float* __restrict__ src, int n) {
    __half* dst = (SEL == 0) ? g_xh : (SEL == 1) ? g_w1h : g_w2h;
    int i = (blockIdx.x * blockDim.x + threadIdx.x) * 4;
    if (i >= n) return;
    float4 v = *reinterpret_cast<const float4*>(src + i);
    __half2 h0 = __floats2half2_rn(v.x, v.y);
    __half2 h1 = __floats2half2_rn(v.z, v.w);
    *reinterpret_cast<__half2*>(dst + i)     = h0;
    *reinterpret_cast<__half2*>(dst + i + 2) = h1;
}

// ---------------- router: logits -> softmax probs ----------------
__global__ void router_kernel(const float* __restrict__ x,
                              const float* __restrict__ rw,
                              const float* __restrict__ rb,
                              float* __restrict__ dout_probs) {
    int gwarp = (blockIdx.x * blockDim.x + threadIdx.x) >> 5;  // token id
    int lane  = threadIdx.x & 31;
    if (gwarp >= T_TOK) return;
    const float* xr = x + (size_t)gwarp * D_DIM;
    float xv[32];
#pragma unroll
    for (int i = 0; i < 32; i++) xv[i] = xr[lane + 32 * i];

    float logit[E_NUM];
#pragma unroll
    for (int e = 0; e < E_NUM; e++) {
        float s = 0.f;
#pragma unroll
        for (int i = 0; i < 32; i++) s += xv[i] * rw[(lane + 32 * i) * E_NUM + e];
#pragma unroll
        for (int o = 16; o; o >>= 1) s += __shfl_xor_sync(0xffffffffu, s, o);
        logit[e] = s + rb[e];
    }
    if (lane == 0) {
        float m = logit[0];
#pragma unroll
        for (int e = 1; e < E_NUM; e++) m = fmaxf(m, logit[e]);
        float p[E_NUM], sum = 0.f;
#pragma unroll
        for (int e = 0; e < E_NUM; e++) { p[e] = expf(logit[e] - m); sum += p[e]; }
        float inv = 1.f / sum;
#pragma unroll
        for (int e = 0; e < E_NUM; e++) {
            float v = p[e] * inv;
            g_probs[gwarp * E_NUM + e]     = v;
            dout_probs[gwarp * E_NUM + e]  = v;
        }
    }
}

// ---------------- out init: y = sum_e probs[t,e]*fc2_bias[e,:] ----------------
__global__ void init_out_kernel(const float* __restrict__ fc2b, float* __restrict__ y) {
    int i = blockIdx.x * blockDim.x + threadIdx.x;
    if (i >= T_TOK * D_DIM) return;
    int t = i / D_DIM, d = i % D_DIM;
    float s = 0.f;
#pragma unroll
    for (int e = 0; e < E_NUM; e++) s += g_probs[t * E_NUM + e] * fc2b[e * D_DIM + d];
    y[i] = s;
}

__device__ __forceinline__ float gelu_exact(float v) {
    return 0.5f * v * (1.0f + erff(v * 0.70710678118654752f));
}

// ---------------- fused GEMMs ----------------
// MODE 1: h'[t, e*H+n] = probs[t,e]*gelu(x@W1_e + b1_e)   (A=g_xh, B=g_w1h)
// MODE 2: y[t,d] += h' @ W2flat   (split-K over blockIdx.z, atomicAdd)
template <int MODE>
__global__ __launch_bounds__(256, 2)
void gemm_kernel(const float* __restrict__ fc1b, float* __restrict__ yout) {
    __shared__ __half As[2][BM][BK + PADA];
    __shared__ __half Bs[2][BK][BN + PADB];

    const int tid  = threadIdx.x;
    const int lane = tid & 31;
    const int warp = tid >> 5;
    const int wm = warp >> 2;   // 0..1 (64 rows each)
    const int wn = warp & 3;    // 0..3 (32 cols each)

    const int bn  = blockIdx.x;
    const int bm  = blockIdx.y;
    const int bz  = blockIdx.z;

    const __half* A;
    const __half* B;
    int lda, ldb, kIters;
    if (MODE == 1) {
        A = g_xh + (size_t)bm * BM * D_DIM;
        lda = D_DIM;
        B = g_w1h + (size_t)bz * D_DIM * H_DIM + bn * BN;
        ldb = H_DIM;
        kIters = D_DIM / BK;            // 32
    } else {
        const int kOff = bz * (K2 / KSPLIT2);  // 8192 per split
        A = g_hb + (size_t)bm * BM * K2 + kOff;
        lda = K2;
        B = g_w2h + (size_t)kOff * D_DIM + bn * BN;
        ldb = D_DIM;
        kIters = (K2 / KSPLIT2) / BK;   // 256
    }

    auto loadTiles = [&](int buf, int kt) {
        const int k0 = kt * BK;
#pragma unroll
        for (int i = 0; i < 2; i++) {                       // A: 512 x 16B chunks
            int c = tid + i * 256;
            int row = c >> 2, off = (c & 3) * 8;
            const __half* gp = A + (size_t)row * lda + k0 + off;
            unsigned int sp = (unsigned int)__cvta_generic_to_shared(&As[buf][row][off]);
            asm volatile("cp.async.cg.shared.global [%0], [%1], 16;\n" :: "r"(sp), "l"(gp));
        }
#pragma unroll
        for (int i = 0; i < 2; i++) {                       // B: 512 x 16B chunks
            int c = tid + i * 256;
            int row = c >> 4, off = (c & 15) * 8;
            const __half* gp = B + (size_t)(k0 + row) * ldb + off;
            unsigned int sp = (unsigned int)__cvta_generic_to_shared(&Bs[buf][row][off]);
            asm volatile("cp.async.cg.shared.global [%0], [%1], 16;\n" :: "r"(sp), "l"(gp));
        }
        asm volatile("cp.async.commit_group;\n" ::);
    };

    float acc[4][4][4];
#pragma unroll
    for (int mf = 0; mf < 4; mf++)
#pragma unroll
        for (int nf = 0; nf < 4; nf++)
#pragma unroll
            for (int i = 0; i < 4; i++) acc[mf][nf][i] = 0.f;

    loadTiles(0, 0);
    for (int kt = 0; kt < kIters; kt++) {
        if (kt + 1 < kIters) {
            loadTiles((kt + 1) & 1, kt + 1);
            asm volatile("cp.async.wait_group 1;\n" ::);
        } else {
            asm volatile("cp.async.wait_group 0;\n" ::);
        }
        __syncthreads();
        const int buf = kt & 1;

#pragma unroll
        for (int ks = 0; ks < 2; ks++) {
            const int kb = ks * 16;
            unsigned int a[4][4];
            unsigned int b[4][2];
#pragma unroll
            for (int mf = 0; mf < 4; mf++) {
                int mrow = wm * 64 + mf * 16 + (lane & 15);
                unsigned int addr = (unsigned int)__cvta_generic_to_shared(
                    &As[buf][mrow][kb + (lane >> 4) * 8]);
                asm volatile("ldmatrix.sync.aligned.m8n8.x4.shared.b16 {%0,%1,%2,%3}, [%4];\n"
                             : "=r"(a[mf][0]), "=r"(a[mf][1]), "=r"(a[mf][2]), "=r"(a[mf][3])
                             : "r"(addr));
            }
#pragma unroll
            for (int nf2 = 0; nf2 < 2; nf2++) {
                int ncol = wn * 32 + nf2 * 16 + (lane >> 4) * 8;
                unsigned int r0, r1, r2, r3;
                unsigned int addr = (unsigned int)__cvta_generic_to_shared(
                    &Bs[buf][kb + (lane & 15)][ncol]);
                asm volatile("ldmatrix.sync.aligned.m8n8.x4.trans.shared.b16 {%0,%1,%2,%3}, [%4];\n"
                             : "=r"(r0), "=r"(r1), "=r"(r2), "=r"(r3)
                             : "r"(addr));
                b[nf2 * 2][0] = r0; b[nf2 * 2][1] = r1;
                b[nf2 * 2 + 1][0] = r2; b[nf2 * 2 + 1][1] = r3;
            }
#pragma unroll
            for (int mf = 0; mf < 4; mf++)
#pragma unroll
                for (int nf = 0; nf < 4; nf++) {
                    asm volatile(
                        "mma.sync.aligned.m16n8k16.row.col.f32.f16.f16.f32 "
                        "{%0,%1,%2,%3}, {%4,%5,%6,%7}, {%8,%9}, {%0,%1,%2,%3};\n"
                        : "+f"(acc[mf][nf][0]), "+f"(acc[mf][nf][1]),
                          "+f"(acc[mf][nf][2]), "+f"(acc[mf][nf][3])
                        : "r"(a[mf][0]), "r"(a[mf][1]), "r"(a[mf][2]), "r"(a[mf][3]),
                          "r"(b[nf][0]), "r"(b[nf][1]));
                }
        }
        __syncthreads();
    }

    // ---------------- epilogue ----------------
    const int mBase = bm * BM + wm * 64;
    const int nBase = bn * BN + wn * 32;
    if (MODE == 1) {
        const int e = bz;
#pragma unroll
        for (int mf = 0; mf < 4; mf++) {
            int r0 = mBase + mf * 16 + (lane >> 2);
#pragma unroll
            for (int nf = 0; nf < 4; nf++) {
                int c0 = nBase + nf * 8 + (lane & 3) * 2;
                float bb0 = fc1b[e * H_DIM + c0];
                float bb1 = fc1b[e * H_DIM + c0 + 1];
#pragma unroll
                for (int h = 0; h < 2; h++) {
                    int r = r0 + h * 8;
                    float p = g_probs[r * E_NUM + e];
                    float v0 = gelu_exact(acc[mf][nf][h * 2 + 0] + bb0) * p;
                    float v1 = gelu_exact(acc[mf][nf][h * 2 + 1] + bb1) * p;
                    *reinterpret_cast<__half2*>(
                        &g_hb[(size_t)r * K2 + e * H_DIM + c0]) = __floats2half2_rn(v0, v1);
                }
            }
        }
    } else {
#pragma unroll
        for (int mf = 0; mf < 4; mf++) {
            int r0 = mBase + mf * 16 + (lane >> 2);
#pragma unroll
            for (int nf = 0; nf < 4; nf++) {
                int c0 = nBase + nf * 8 + (lane & 3) * 2;
                atomicAdd(&yout[(size_t)r0 * D_DIM + c0],       acc[mf][nf][0]);
                atomicAdd(&yout[(size_t)r0 * D_DIM + c0 + 1],   acc[mf][nf][1]);
                atomicAdd(&yout[(size_t)(r0 + 8) * D_DIM + c0],     acc[mf][nf][2]);
                atomicAdd(&yout[(size_t)(r0 + 8) * D_DIM + c0 + 1], acc[mf][nf][3]);
            }
        }
    }
}

// ---------------- launch ----------------
extern "C" void kernel_launch(void* const* d_in, const int* in_sizes, int n_in,
                              void* d_out, int out_size) {
    const float* x   = (const float*)d_in[0];
    const float* rw  = (const float*)d_in[1];
    const float* rb  = (const float*)d_in[2];
    const float* w1  = (const float*)d_in[3];
    const float* b1  = (const float*)d_in[4];
    const float* w2  = (const float*)d_in[5];
    const float* b2  = (const float*)d_in[6];

    float* y      = (float*)d_out;                 // [T, D]
    float* dprobs = y + (size_t)T_TOK * D_DIM;     // [T, E]

    const int nX = T_TOK * D_DIM;                  // 2,097,152
    const int nW = E_NUM * D_DIM * H_DIM;          // 33,554,432

    f2h_kernel<0><<<nX / 4 / 256, 256>>>(x, nX);
    f2h_kernel<1><<<nW / 4 / 256, 256>>>(w1, nW);
    f2h_kernel<2><<<nW / 4 / 256, 256>>>(w2, nW);

    router_kernel<<<T_TOK / 8, 256>>>(x, rw, rb, dprobs);
    init_out_kernel<<<(T_TOK * D_DIM) / 256, 256>>>(b2, y);

    dim3 g1(H_DIM / BN, T_TOK / BM, E_NUM);        // (32, 16, 8)
    gemm_kernel<1><<<g1, 256>>>(b1, nullptr);

    dim3 g2(D_DIM / BN, T_TOK / BM, KSPLIT2);      // (8, 16, 4)
    gemm_kernel<2><<<g2, 256>>>(nullptr, y);
}